// round 1
// baseline (speedup 1.0000x reference)
#include <cuda_runtime.h>
#include <cuda_bf16.h>

// Problem constants (fixed by reference setup_inputs)
#define N_ROWS 262144      // 2^18
#define DIM    512
#define REG_C  0.1
#define EPS_F  2.2204460492503131e-16f

// Scratch (no allocations allowed)
__device__ float  g_out[N_ROWS];
__device__ double g_partial[256][2];

// ---------------------------------------------------------------------------
// 1) Matvec: out[i] = dot(x[i,:], w) + b  — one warp per row, coalesced f4
// ---------------------------------------------------------------------------
__global__ void matvec_kernel(const float* __restrict__ x,
                              const float* __restrict__ w,
                              const float* __restrict__ b) {
    int warp = (blockIdx.x * blockDim.x + threadIdx.x) >> 5;
    int lane = threadIdx.x & 31;
    if (warp >= N_ROWS) return;

    const float4* xr = reinterpret_cast<const float4*>(x + (size_t)warp * DIM);
    const float4* w4 = reinterpret_cast<const float4*>(w);

    float acc = 0.f;
#pragma unroll
    for (int it = 0; it < 4; it++) {
        float4 xv = xr[lane + it * 32];
        float4 wv = __ldg(&w4[lane + it * 32]);
        acc += xv.x * wv.x + xv.y * wv.y + xv.z * wv.z + xv.w * wv.w;
    }
#pragma unroll
    for (int o = 16; o > 0; o >>= 1)
        acc += __shfl_xor_sync(0xffffffffu, acc, o);

    if (lane == 0) g_out[warp] = acc + b[0];
}

// ---------------------------------------------------------------------------
// 2) Bitonic sort of g_out (N = 2^18), tile = 4096 elems in shared memory
// ---------------------------------------------------------------------------
#define TILE 4096

// All stages k = 2 .. 4096 (every stride fits inside a 4096-aligned tile)
__global__ __launch_bounds__(1024) void bitonic_init_kernel() {
    __shared__ float s[TILE];
    int base = blockIdx.x * TILE;
    for (int i = threadIdx.x; i < TILE; i += 1024) s[i] = g_out[base + i];
    __syncthreads();
    for (int k = 2; k <= TILE; k <<= 1) {
        for (int j = k >> 1; j > 0; j >>= 1) {
            for (int p = threadIdx.x; p < TILE / 2; p += 1024) {
                int i = ((p & ~(j - 1)) << 1) | (p & (j - 1));
                int r = i | j;
                bool asc = (((base + i) & k) == 0);
                float a = s[i], bb = s[r];
                if ((a > bb) == asc) { s[i] = bb; s[r] = a; }
            }
            __syncthreads();
        }
    }
    for (int i = threadIdx.x; i < TILE; i += 1024) g_out[base + i] = s[i];
}

// One global compare-exchange pass for a given (k, j), j >= 4096
__global__ void bitonic_global_kernel(int k, int j) {
    int p = blockIdx.x * blockDim.x + threadIdx.x;   // 0 .. N/2-1
    int i = ((p & ~(j - 1)) << 1) | (p & (j - 1));
    int r = i | j;
    bool asc = ((i & k) == 0);
    float a = g_out[i], bb = g_out[r];
    if ((a > bb) == asc) { g_out[i] = bb; g_out[r] = a; }
}

// Finish strides j = 2048 .. 1 for a given k inside shared tiles
__global__ __launch_bounds__(1024) void bitonic_finish_kernel(int k) {
    __shared__ float s[TILE];
    int base = blockIdx.x * TILE;
    for (int i = threadIdx.x; i < TILE; i += 1024) s[i] = g_out[base + i];
    __syncthreads();
    // direction is constant per tile (k >= 8192 > TILE)
    bool asc = ((base & k) == 0);
    for (int j = TILE / 2; j > 0; j >>= 1) {
        for (int p = threadIdx.x; p < TILE / 2; p += 1024) {
            int i = ((p & ~(j - 1)) << 1) | (p & (j - 1));
            int r = i | j;
            float a = s[i], bb = s[r];
            if ((a > bb) == asc) { s[i] = bb; s[r] = a; }
        }
        __syncthreads();
    }
    for (int i = threadIdx.x; i < TILE; i += 1024) g_out[base + i] = s[i];
}

// ---------------------------------------------------------------------------
// 3) Reductions over sorted array:  sum_s = Σ s_i,  sum_cs = Σ (2i-(n-1)) s_i
// ---------------------------------------------------------------------------
__global__ void reduce1_kernel() {
    __shared__ double sh_s[256], sh_cs[256];
    int t = threadIdx.x;
    int blk = blockIdx.x;                // 256 blocks
    double sum_s = 0.0, sum_cs = 0.0;
    // each block handles a contiguous 1024-element slice
    int base = blk * (N_ROWS / 256);
#pragma unroll 4
    for (int i = t; i < N_ROWS / 256; i += 256) {
        int gi = base + i;
        double v = (double)g_out[gi];
        double coef = 2.0 * (double)gi - (double)(N_ROWS - 1);
        sum_s  += v;
        sum_cs += coef * v;
    }
    sh_s[t] = sum_s; sh_cs[t] = sum_cs;
    __syncthreads();
    for (int o = 128; o > 0; o >>= 1) {
        if (t < o) { sh_s[t] += sh_s[t + o]; sh_cs[t] += sh_cs[t + o]; }
        __syncthreads();
    }
    if (t == 0) { g_partial[blk][0] = sh_s[0]; g_partial[blk][1] = sh_cs[0]; }
}

__global__ void reduce2_kernel(float* __restrict__ out) {
    __shared__ double sh_s[256], sh_cs[256];
    int t = threadIdx.x;
    sh_s[t]  = g_partial[t][0];
    sh_cs[t] = g_partial[t][1];
    __syncthreads();
    for (int o = 128; o > 0; o >>= 1) {
        if (t < o) { sh_s[t] += sh_s[t + o]; sh_cs[t] += sh_cs[t + o]; }
        __syncthreads();
    }
    if (t == 0) {
        double loss = -sh_s[0] + (REG_C / (double)N_ROWS) * sh_cs[0];
        out[0] = (float)loss;
        // sorted ascending -> g_out[0] is the min; verified iff min + eps > 0
        float tmin = g_out[0] + EPS_F;
        out[1] = (tmin > 0.0f) ? 1.0f : 0.0f;
    }
}

// ---------------------------------------------------------------------------
// Launch
// ---------------------------------------------------------------------------
extern "C" void kernel_launch(void* const* d_in, const int* in_sizes, int n_in,
                              void* d_out, int out_size) {
    const float* x = (const float*)d_in[0];
    const float* w = (const float*)d_in[1];
    const float* b = (const float*)d_in[2];
    float* out = (float*)d_out;

    // 1) matvec: 8 warps/block -> 32768 blocks
    matvec_kernel<<<N_ROWS / 8, 256>>>(x, w, b);

    // 2) bitonic sort
    bitonic_init_kernel<<<N_ROWS / TILE, 1024>>>();
    for (int k = TILE * 2; k <= N_ROWS; k <<= 1) {
        for (int j = k >> 1; j >= TILE; j >>= 1) {
            bitonic_global_kernel<<<(N_ROWS / 2) / 256, 256>>>(k, j);
        }
        bitonic_finish_kernel<<<N_ROWS / TILE, 1024>>>(k);
    }

    // 3) reductions + finalize
    reduce1_kernel<<<256, 256>>>();
    reduce2_kernel<<<1, 256>>>(out);
}